// round 8
// baseline (speedup 1.0000x reference)
#include <cuda_runtime.h>

#define BB 4096
#define TT 2048
#define HH 10
#define NPAIR 2048   // elements 0..2047 = "A", 2048..4095 = "B"

union F2U { float2 f; unsigned long long u; };

__device__ __forceinline__ float2 ffma2(float2 a, float2 b, float2 c) {
    F2U ua, ub, uc, ud;
    ua.f = a; ub.f = b; uc.f = c;
    asm("fma.rn.f32x2 %0, %1, %2, %3;" : "=l"(ud.u) : "l"(ua.u), "l"(ub.u), "l"(uc.u));
    return ud.f;
}

__device__ __forceinline__ float tanh_fast(float x) {
    float y;
    asm("tanh.approx.f32 %0, %1;" : "=f"(y) : "f"(x));
    return y;
}

// TWO elements per thread (A = p, B = p + 2048), one hidden unit per thread,
// 3 element-pairs per warp (lanes 0..29). 683 active warps in 5-warp CTAs,
// grid=137 -> 1 CTA/SM, ~5 warps/SM (1-2 per SMSP): halves scheduler
// interference on the recurrence chain while the A/B chains interleave as
// per-thread ILP. h exchanged via double-buffered warp-private SMEM
// broadcast (no syncwarp needed; warp converged, SMEM pipe in-order).
// Gates: f32x2 packed FMA chains; activations MUFU.TANH (sigmoid 0.5-scale
// folded into weights/biases). One STG.128 per element per 4 steps.
__global__ void __launch_bounds__(160, 1) lstm_fused_kernel(
    const float* __restrict__ x,      // [B, T, 1]
    const float* __restrict__ W_ih,   // [4H, 1]
    const float* __restrict__ W_hh,   // [4H, H]
    const float* __restrict__ b_ih,   // [4H]
    const float* __restrict__ b_hh,   // [4H]
    const float* __restrict__ W_out,  // [1, H]
    const float* __restrict__ b_out,  // [1]
    float* __restrict__ out)          // [B, T, 1]
{
    // [buf][warp][AB][slot][12 floats]  (slot 3 = scratch for idle lanes)
    __shared__ float hx[2][5][2][4][12];

    const int tid  = threadIdx.x;
    const int lane = tid & 31;
    const int w    = tid >> 5;

    int ew = lane / HH;              // 0..2 pair-slot, 3 = idle lanes 30,31
    int j  = lane - ew * HH;         // hidden unit 0..9 (idle: 0,1)
    bool active = (ew < 3);

    int p = (blockIdx.x * 5 + w) * 3 + ew;
    if (p >= NPAIR) active = false;
    const int pa = active ? p : 0;
    const int pb = pa + NPAIR;

    // zero this warp's exchange buffers (h0 = 0 and scratch slots)
    {
        float* s0 = &hx[0][w][0][0][0];
        float* s1 = &hx[1][w][0][0][0];
        for (int i = lane; i < 2 * 4 * 12; i += 32) { s0[i] = 0.0f; s1[i] = 0.0f; }
    }

    // ---- per-thread constants, shared by A and B (same j) ----
    float2 wi2[5], wf2[5], wg2[5], wo2[5], wout2[5];
#pragma unroll
    for (int m = 0; m < 5; m++) {
        wi2[m] = make_float2(0.5f * W_hh[(0 * HH + j) * HH + 2 * m],
                             0.5f * W_hh[(0 * HH + j) * HH + 2 * m + 1]);
        wf2[m] = make_float2(0.5f * W_hh[(1 * HH + j) * HH + 2 * m],
                             0.5f * W_hh[(1 * HH + j) * HH + 2 * m + 1]);
        wg2[m] = make_float2(W_hh[(2 * HH + j) * HH + 2 * m],
                             W_hh[(2 * HH + j) * HH + 2 * m + 1]);
        wo2[m] = make_float2(0.5f * W_hh[(3 * HH + j) * HH + 2 * m],
                             0.5f * W_hh[(3 * HH + j) * HH + 2 * m + 1]);
        wout2[m] = make_float2(W_out[2 * m], W_out[2 * m + 1]);
    }
    const float2 wxi2 = make_float2(0.5f * W_ih[0 * HH + j], 0.0f);
    const float2 wxf2 = make_float2(0.5f * W_ih[1 * HH + j], 0.0f);
    const float2 wxg2 = make_float2(       W_ih[2 * HH + j], 0.0f);
    const float2 wxo2 = make_float2(0.5f * W_ih[3 * HH + j], 0.0f);
    const float2 bi2 = make_float2(0.5f * (b_ih[0 * HH + j] + b_hh[0 * HH + j]), 0.0f);
    const float2 bf2 = make_float2(0.5f * (b_ih[1 * HH + j] + b_hh[1 * HH + j]), 0.0f);
    const float2 bg2 = make_float2(       (b_ih[2 * HH + j] + b_hh[2 * HH + j]), 0.0f);
    const float2 bo2 = make_float2(0.5f * (b_ih[3 * HH + j] + b_hh[3 * HH + j]), 0.0f);
    const float2 bout2 = make_float2(b_out[0], 0.0f);

    const float* xpA = x   + (size_t)pa * TT;
    const float* xpB = x   + (size_t)pb * TT;
    float*       opA = out + (size_t)pa * TT;
    float*       opB = out + (size_t)pb * TT;
    const bool do_out = active && (j == 0);

    const float* rdA0 = &hx[0][w][0][ew][0];
    const float* rdA1 = &hx[1][w][0][ew][0];
    const float* rdB0 = &hx[0][w][1][ew][0];
    const float* rdB1 = &hx[1][w][1][ew][0];
    float* wrA0 = &hx[0][w][0][ew][j];
    float* wrA1 = &hx[1][w][0][ew][j];
    float* wrB0 = &hx[0][w][1][ew][j];
    float* wrB1 = &hx[1][w][1][ew][j];

    float cA = 0.0f, cB = 0.0f;
    float4 obufA, obufB;

    // One step for both elements; A/B statements interleaved for ILP.
    // Returns the two projections of h[t-1] via refs.
    auto step2 = [&](float xa, float xb,
                     const float* rdA, const float* rdB,
                     float* wrA, float* wrB,
                     float& poA, float& poB) {
        float4 Aa = *(const float4*)rdA;
        float4 Ba = *(const float4*)rdB;
        float4 Ab = *(const float4*)(rdA + 4);
        float4 Bb = *(const float4*)(rdB + 4);
        float2 Ac = *(const float2*)(rdA + 8);
        float2 Bc = *(const float2*)(rdB + 8);
        float2 hA[5] = { make_float2(Aa.x, Aa.y), make_float2(Aa.z, Aa.w),
                         make_float2(Ab.x, Ab.y), make_float2(Ab.z, Ab.w), Ac };
        float2 hB[5] = { make_float2(Ba.x, Ba.y), make_float2(Ba.z, Ba.w),
                         make_float2(Bb.x, Bb.y), make_float2(Bb.z, Bb.w), Bc };

        float2 oaccA = ffma2(hA[0], wout2[0], bout2);
        float2 oaccB = ffma2(hB[0], wout2[0], bout2);
#pragma unroll
        for (int m = 1; m < 5; m++) {
            oaccA = ffma2(hA[m], wout2[m], oaccA);
            oaccB = ffma2(hB[m], wout2[m], oaccB);
        }

        float2 xa2 = make_float2(xa, xa);
        float2 xb2 = make_float2(xb, xb);
        float2 aIA = ffma2(xa2, wxi2, bi2), aIB = ffma2(xb2, wxi2, bi2);
        float2 aFA = ffma2(xa2, wxf2, bf2), aFB = ffma2(xb2, wxf2, bf2);
        float2 aGA = ffma2(xa2, wxg2, bg2), aGB = ffma2(xb2, wxg2, bg2);
        float2 aOA = ffma2(xa2, wxo2, bo2), aOB = ffma2(xb2, wxo2, bo2);
#pragma unroll
        for (int m = 0; m < 5; m++) {
            aIA = ffma2(hA[m], wi2[m], aIA);  aIB = ffma2(hB[m], wi2[m], aIB);
            aFA = ffma2(hA[m], wf2[m], aFA);  aFB = ffma2(hB[m], wf2[m], aFB);
            aGA = ffma2(hA[m], wg2[m], aGA);  aGB = ffma2(hB[m], wg2[m], aGB);
            aOA = ffma2(hA[m], wo2[m], aOA);  aOB = ffma2(hB[m], wo2[m], aOB);
        }
        float siA = fmaf(tanh_fast(aIA.x + aIA.y), 0.5f, 0.5f);
        float siB = fmaf(tanh_fast(aIB.x + aIB.y), 0.5f, 0.5f);
        float sfA = fmaf(tanh_fast(aFA.x + aFA.y), 0.5f, 0.5f);
        float sfB = fmaf(tanh_fast(aFB.x + aFB.y), 0.5f, 0.5f);
        float gA  =      tanh_fast(aGA.x + aGA.y);
        float gB  =      tanh_fast(aGB.x + aGB.y);
        float soA = fmaf(tanh_fast(aOA.x + aOA.y), 0.5f, 0.5f);
        float soB = fmaf(tanh_fast(aOB.x + aOB.y), 0.5f, 0.5f);
        cA = fmaf(sfA, cA, siA * gA);
        cB = fmaf(sfB, cB, siB * gB);
        float hAn = soA * tanh_fast(cA);
        float hBn = soB * tanh_fast(cB);
        *wrA = hAn;
        *wrB = hBn;
        poA = oaccA.x + oaccA.y;
        poB = oaccB.x + oaccB.y;
    };

    // ---- t = 0..3: buf parity 0,1,0,1; first projection (h=-1) discarded ----
    float4 x4A = *(const float4*)xpA;
    float4 x4B = *(const float4*)xpB;
    float4 xn4A = *(const float4*)(xpA + 4);
    float4 xn4B = *(const float4*)(xpB + 4);
    float dA, dB;
    step2(x4A.x, x4B.x, rdA0, rdB0, wrA1, wrB1, dA, dB);
    step2(x4A.y, x4B.y, rdA1, rdB1, wrA0, wrB0, obufA.x, obufB.x);  // out[0]
    step2(x4A.z, x4B.z, rdA0, rdB0, wrA1, wrB1, obufA.y, obufB.y);  // out[1]
    step2(x4A.w, x4B.w, rdA1, rdB1, wrA0, wrB0, obufA.z, obufB.z);  // out[2]
    x4A = xn4A; x4B = xn4B;

    // ---- blocks 1..511 ----
    for (int u = 1; u < TT / 4; u++) {
        int un = (u + 1 < TT / 4) ? (u + 1) : u;
        xn4A = *(const float4*)(xpA + 4 * un);
        xn4B = *(const float4*)(xpB + 4 * un);
        step2(x4A.x, x4B.x, rdA0, rdB0, wrA1, wrB1, obufA.w, obufB.w);  // out[4u-1]
        if (do_out) {
            *(float4*)(opA + 4 * u - 4) = obufA;
            *(float4*)(opB + 4 * u - 4) = obufB;
        }
        step2(x4A.y, x4B.y, rdA1, rdB1, wrA0, wrB0, obufA.x, obufB.x);  // out[4u]
        step2(x4A.z, x4B.z, rdA0, rdB0, wrA1, wrB1, obufA.y, obufB.y);  // out[4u+1]
        step2(x4A.w, x4B.w, rdA1, rdB1, wrA0, wrB0, obufA.z, obufB.z);  // out[4u+2]
        x4A = xn4A; x4B = xn4B;
    }

    // ---- final: out[T-1] from h[T-1] (sits in buf 0) ----
    {
        float4 Aa = *(const float4*)rdA0;
        float4 Ba = *(const float4*)rdB0;
        float4 Ab = *(const float4*)(rdA0 + 4);
        float4 Bb = *(const float4*)(rdB0 + 4);
        float2 Ac = *(const float2*)(rdA0 + 8);
        float2 Bc = *(const float2*)(rdB0 + 8);
        float2 hA[5] = { make_float2(Aa.x, Aa.y), make_float2(Aa.z, Aa.w),
                         make_float2(Ab.x, Ab.y), make_float2(Ab.z, Ab.w), Ac };
        float2 hB[5] = { make_float2(Ba.x, Ba.y), make_float2(Ba.z, Ba.w),
                         make_float2(Bb.x, Bb.y), make_float2(Bb.z, Bb.w), Bc };
        float2 oaccA = ffma2(hA[0], wout2[0], bout2);
        float2 oaccB = ffma2(hB[0], wout2[0], bout2);
#pragma unroll
        for (int m = 1; m < 5; m++) {
            oaccA = ffma2(hA[m], wout2[m], oaccA);
            oaccB = ffma2(hB[m], wout2[m], oaccB);
        }
        obufA.w = oaccA.x + oaccA.y;
        obufB.w = oaccB.x + oaccB.y;
        if (do_out) {
            *(float4*)(opA + TT - 4) = obufA;
            *(float4*)(opB + TT - 4) = obufB;
        }
    }
}

extern "C" void kernel_launch(void* const* d_in, const int* in_sizes, int n_in,
                              void* d_out, int out_size) {
    const float* x     = (const float*)d_in[0];
    const float* W_ih  = (const float*)d_in[1];
    const float* W_hh  = (const float*)d_in[2];
    const float* b_ih  = (const float*)d_in[3];
    const float* b_hh  = (const float*)d_in[4];
    const float* W_out = (const float*)d_in[5];
    const float* b_out = (const float*)d_in[6];
    float* out = (float*)d_out;

    // 5-warp CTAs, 3 pairs/warp (6 elements): 30 elements/CTA,
    // grid = ceil(2048 pairs / 15) = 137 -> 1 CTA/SM, ~5 warps/SM
    const int pairs_per_block = 15;
    const int grid = (NPAIR + pairs_per_block - 1) / pairs_per_block;  // 137
    lstm_fused_kernel<<<grid, 160>>>(x, W_ih, W_hh, b_ih, b_hh, W_out, b_out, out);
}

// round 9
// speedup vs baseline: 1.3559x; 1.3559x over previous
#include <cuda_runtime.h>

#define BB 4096
#define TT 2048
#define HH 10

union F2U { float2 f; unsigned long long u; };

__device__ __forceinline__ float2 ffma2(float2 a, float2 b, float2 c) {
    F2U ua, ub, uc, ud;
    ua.f = a; ub.f = b; uc.f = c;
    asm("fma.rn.f32x2 %0, %1, %2, %3;" : "=l"(ud.u) : "l"(ua.u), "l"(ub.u), "l"(uc.u));
    return ud.f;
}

__device__ __forceinline__ float tanh_fast(float x) {
    float y;
    asm("tanh.approx.f32 %0, %1;" : "=f"(y) : "f"(x));
    return y;
}

// One hidden unit per thread, 3 LSTM elements per warp (lanes 0..29).
// 10-warp CTAs, grid=137 -> <=1 CTA/SM: uniform 10 warps/SM.
// Warps are DE-PHASED at start (__nanosleep(w*40)) so the per-step MUFU/FMA
// bursts of co-resident warps stop colliding: with identical per-step work the
// initial offset persists for all 2048 steps.
// h exchanged via double-buffered warp-private SMEM broadcast (no syncwarp:
// warp converged, per-warp SMEM pipe in-order). Gates: f32x2 packed FMA
// chains; activations MUFU.TANH (sigmoid 0.5-scale folded into weights).
// One STG.128 per 4 steps; x via float4; last block peeled (no clamp select).
__global__ void __launch_bounds__(320, 1) lstm_fused_kernel(
    const float* __restrict__ x,      // [B, T, 1]
    const float* __restrict__ W_ih,   // [4H, 1]
    const float* __restrict__ W_hh,   // [4H, H]
    const float* __restrict__ b_ih,   // [4H]
    const float* __restrict__ b_hh,   // [4H]
    const float* __restrict__ W_out,  // [1, H]
    const float* __restrict__ b_out,  // [1]
    float* __restrict__ out)          // [B, T, 1]
{
    // [buf][warp][slot][12 floats]  (slot 3 = scratch for idle lanes)
    __shared__ float hx[2][10][4][12];

    const int tid  = threadIdx.x;
    const int lane = tid & 31;
    const int w    = tid >> 5;

    int ew = lane / HH;              // 0..2 element, 3 = idle lanes 30,31
    int j  = lane - ew * HH;         // hidden unit 0..9 (idle: 0,1)
    bool active = (ew < 3);

    int b = (blockIdx.x * 10 + w) * 3 + ew;
    if (b >= BB) active = false;
    const int bb = active ? b : 0;

    // zero this warp's exchange buffers (h0 = 0 and scratch slots)
    {
        float* s0 = &hx[0][w][0][0];
        float* s1 = &hx[1][w][0][0];
        for (int i = lane; i < 4 * 12; i += 32) { s0[i] = 0.0f; s1[i] = 0.0f; }
    }
    // no cross-warp smem dependency: each warp only touches hx[*][w][*][*]

    // ---- per-thread constants (sigmoid gates pre-scaled by 0.5) ----
    float2 wi2[5], wf2[5], wg2[5], wo2[5], wout2[5];
#pragma unroll
    for (int m = 0; m < 5; m++) {
        wi2[m] = make_float2(0.5f * W_hh[(0 * HH + j) * HH + 2 * m],
                             0.5f * W_hh[(0 * HH + j) * HH + 2 * m + 1]);
        wf2[m] = make_float2(0.5f * W_hh[(1 * HH + j) * HH + 2 * m],
                             0.5f * W_hh[(1 * HH + j) * HH + 2 * m + 1]);
        wg2[m] = make_float2(W_hh[(2 * HH + j) * HH + 2 * m],
                             W_hh[(2 * HH + j) * HH + 2 * m + 1]);
        wo2[m] = make_float2(0.5f * W_hh[(3 * HH + j) * HH + 2 * m],
                             0.5f * W_hh[(3 * HH + j) * HH + 2 * m + 1]);
        wout2[m] = make_float2(W_out[2 * m], W_out[2 * m + 1]);
    }
    const float2 wxi2 = make_float2(0.5f * W_ih[0 * HH + j], 0.0f);
    const float2 wxf2 = make_float2(0.5f * W_ih[1 * HH + j], 0.0f);
    const float2 wxg2 = make_float2(       W_ih[2 * HH + j], 0.0f);
    const float2 wxo2 = make_float2(0.5f * W_ih[3 * HH + j], 0.0f);
    const float2 bi2 = make_float2(0.5f * (b_ih[0 * HH + j] + b_hh[0 * HH + j]), 0.0f);
    const float2 bf2 = make_float2(0.5f * (b_ih[1 * HH + j] + b_hh[1 * HH + j]), 0.0f);
    const float2 bg2 = make_float2(       (b_ih[2 * HH + j] + b_hh[2 * HH + j]), 0.0f);
    const float2 bo2 = make_float2(0.5f * (b_ih[3 * HH + j] + b_hh[3 * HH + j]), 0.0f);
    const float2 bout2 = make_float2(b_out[0], 0.0f);

    const float* xp = x   + (size_t)bb * TT;
    float*       op = out + (size_t)bb * TT;
    const bool do_out = active && (j == 0);

    const float* rd0 = &hx[0][w][ew][0];   // LDS base, buf 0
    const float* rd1 = &hx[1][w][ew][0];   // LDS base, buf 1
    float*       wr0 = &hx[0][w][ew][j];   // STS addr, buf 0
    float*       wr1 = &hx[1][w][ew][j];   // STS addr, buf 1

    float c = 0.0f;
    float4 obuf;

    // One step: reads h[t-1] from rd, writes h[t] to wr, returns out proj of h[t-1].
    auto step = [&](float xv, const float* rd, float* wr) -> float {
        float4 A = *(const float4*)rd;
        float4 Bv = *(const float4*)(rd + 4);
        float2 C = *(const float2*)(rd + 8);
        float2 hh2[5] = { make_float2(A.x, A.y), make_float2(A.z, A.w),
                          make_float2(Bv.x, Bv.y), make_float2(Bv.z, Bv.w), C };

        float2 oacc = ffma2(hh2[0], wout2[0], bout2);
#pragma unroll
        for (int m = 1; m < 5; m++) oacc = ffma2(hh2[m], wout2[m], oacc);

        float2 x2 = make_float2(xv, xv);
        float2 aI = ffma2(x2, wxi2, bi2);
        float2 aF = ffma2(x2, wxf2, bf2);
        float2 aG = ffma2(x2, wxg2, bg2);
        float2 aO = ffma2(x2, wxo2, bo2);
#pragma unroll
        for (int m = 0; m < 5; m++) {
            aI = ffma2(hh2[m], wi2[m], aI);
            aF = ffma2(hh2[m], wf2[m], aF);
            aG = ffma2(hh2[m], wg2[m], aG);
            aO = ffma2(hh2[m], wo2[m], aO);
        }
        float si = fmaf(tanh_fast(aI.x + aI.y), 0.5f, 0.5f);
        float sf = fmaf(tanh_fast(aF.x + aF.y), 0.5f, 0.5f);
        float g  =      tanh_fast(aG.x + aG.y);
        float so = fmaf(tanh_fast(aO.x + aO.y), 0.5f, 0.5f);
        c = fmaf(sf, c, si * g);
        float h = so * tanh_fast(c);
        *wr = h;   // in-order per-warp SMEM pipe: next step's LDS sees this
        return oacc.x + oacc.y;
    };

    // De-phase co-resident warps so per-step MUFU/FMA bursts don't collide.
    // One-time cost (<=400ns); identical per-step work keeps offsets stable.
    if (w) __nanosleep(w * 40);

    // ---- t = 0..3: buf parity 0,1,0,1; first projection (h=-1) discarded ----
    float4 x4 = *(const float4*)xp;
    float4 xn4 = *(const float4*)(xp + 4);
    (void)step(x4.x, rd0, wr1);
    obuf.x = step(x4.y, rd1, wr0);    // out[0]
    obuf.y = step(x4.z, rd0, wr1);    // out[1]
    obuf.z = step(x4.w, rd1, wr0);    // out[2]
    x4 = xn4;

    // ---- blocks 1..510: unconditional prefetch of block u+1 (<=511) ----
#pragma unroll 2
    for (int u = 1; u < TT / 4 - 1; u++) {
        xn4 = *(const float4*)(xp + 4 * u + 4);
        obuf.w = step(x4.x, rd0, wr1);   // out[4u-1]
        if (do_out) *(float4*)(op + 4 * u - 4) = obuf;
        obuf.x = step(x4.y, rd1, wr0);   // out[4u]
        obuf.y = step(x4.z, rd0, wr1);   // out[4u+1]
        obuf.z = step(x4.w, rd1, wr0);   // out[4u+2]
        x4 = xn4;
    }

    // ---- peeled last block u = 511 (t = 2044..2047), no prefetch ----
    {
        const int u = TT / 4 - 1;
        obuf.w = step(x4.x, rd0, wr1);   // out[4u-1]
        if (do_out) *(float4*)(op + 4 * u - 4) = obuf;
        obuf.x = step(x4.y, rd1, wr0);   // out[4u]
        obuf.y = step(x4.z, rd0, wr1);   // out[4u+1]
        obuf.z = step(x4.w, rd1, wr0);   // out[4u+2]
    }

    // ---- final: out[T-1] from h[T-1] (sits in buf 0) ----
    {
        float4 A = *(const float4*)rd0;
        float4 Bv = *(const float4*)(rd0 + 4);
        float2 C = *(const float2*)(rd0 + 8);
        float2 hh2[5] = { make_float2(A.x, A.y), make_float2(A.z, A.w),
                          make_float2(Bv.x, Bv.y), make_float2(Bv.z, Bv.w), C };
        float2 oacc = ffma2(hh2[0], wout2[0], bout2);
#pragma unroll
        for (int m = 1; m < 5; m++) oacc = ffma2(hh2[m], wout2[m], oacc);
        obuf.w = oacc.x + oacc.y;
        if (do_out) *(float4*)(op + TT - 4) = obuf;
    }
}

extern "C" void kernel_launch(void* const* d_in, const int* in_sizes, int n_in,
                              void* d_out, int out_size) {
    const float* x     = (const float*)d_in[0];
    const float* W_ih  = (const float*)d_in[1];
    const float* W_hh  = (const float*)d_in[2];
    const float* b_ih  = (const float*)d_in[3];
    const float* b_hh  = (const float*)d_in[4];
    const float* W_out = (const float*)d_in[5];
    const float* b_out = (const float*)d_in[6];
    float* out = (float*)d_out;

    // 10-warp CTAs, 30 elements each: 137 CTAs -> <=1 CTA/SM, uniform 10 warps/SM
    const int elems_per_block = 30;
    const int grid = (BB + elems_per_block - 1) / elems_per_block;  // 137
    lstm_fused_kernel<<<grid, 320>>>(x, W_ih, W_hh, b_ih, b_hh, W_out, b_out, out);
}